// round 1
// baseline (speedup 1.0000x reference)
#include <cuda_runtime.h>
#include <math.h>

#define Nn 32
#define Cc 512
#define Pp 1600
#define Kk 64
#define EPSF 1e-12f

#define TP 128     // p-tile for scores kernel
#define CK 32      // c-chunk
#define NPT 13     // ceil(1600/128)
#define PC 32      // p-chunk for agg kernel

// Scratch (no allocations allowed): static device globals
__device__ float g_soft[(size_t)Nn * Kk * Pp];   // 13.1 MB
__device__ float g_agg [(size_t)Nn * Kk * Cc];   // 4 MB
__device__ float g_mass[Nn * Kk];
__device__ float g_gsum[Nn];

// ---------------------------------------------------------------------------
// Kernel 0: zero atomic accumulators (must be reset on every graph replay)
// ---------------------------------------------------------------------------
__global__ void k_zero() {
    int t = blockIdx.x * blockDim.x + threadIdx.x;
    if (t < Nn * Kk) g_mass[t] = 0.f;
    if (t < Nn)      g_gsum[t] = 0.f;
}

// ---------------------------------------------------------------------------
// Kernel 1: scores GEMM (W[64,512] @ X[512,P]) + bias + softmax over k
//           + write soft[n,k,p] + per-block mass partial sums
// Block: 256 threads = 16(tk) x 16(tp); micro-tile 4k x 8p; tile 64k x 128p.
// ---------------------------------------------------------------------------
__global__ __launch_bounds__(256) void k_scores(const float* __restrict__ x,
                                                const float* __restrict__ conv_w,
                                                const float* __restrict__ conv_b) {
    __shared__ float sbuf[Kk * (TP + 2)];   // 8320 floats; reused: xs+ws then ss
    __shared__ float sbias[Kk];

    float* xs = sbuf;              // [CK][TP]            (4096 floats)
    float* ws = sbuf + CK * TP;    // [Kk][CK+1]          (2112 floats)

    const int n     = blockIdx.y;
    const int pbase = blockIdx.x * TP;
    const int tid   = threadIdx.x;
    const int tk    = tid >> 4;    // 0..15
    const int tp    = tid & 15;    // 0..15

    if (tid < Kk) sbias[tid] = conv_b[tid];

    float acc[4][8];
#pragma unroll
    for (int i = 0; i < 4; i++)
#pragma unroll
        for (int j = 0; j < 8; j++) acc[i][j] = 0.f;

    const float* xb = x + (size_t)n * Cc * Pp;

    for (int c0 = 0; c0 < Cc; c0 += CK) {
        __syncthreads();
        // load x chunk [CK][TP] (float4, coalesced; zero-fill OOB p)
        for (int i = tid; i < CK * TP / 4; i += 256) {
            int c  = i >> 5;        // TP/4 = 32 float4 per row
            int p4 = i & 31;
            int p  = pbase + p4 * 4;
            float4 v = make_float4(0.f, 0.f, 0.f, 0.f);
            if (p < Pp) v = *(const float4*)(xb + (size_t)(c0 + c) * Pp + p);
            *(float4*)(xs + c * TP + p4 * 4) = v;
        }
        // load w chunk [Kk][CK] (coalesced, padded rows)
        for (int i = tid; i < Kk * CK; i += 256) {
            int k = i >> 5, c = i & 31;
            ws[k * (CK + 1) + c] = conv_w[k * Cc + c0 + c];
        }
        __syncthreads();

#pragma unroll 8
        for (int c = 0; c < CK; c++) {
            float wv[4], xv[8];
#pragma unroll
            for (int i = 0; i < 4; i++) wv[i] = ws[(tk * 4 + i) * (CK + 1) + c];
#pragma unroll
            for (int j = 0; j < 8; j++) xv[j] = xs[c * TP + tp * 8 + j];
#pragma unroll
            for (int i = 0; i < 4; i++)
#pragma unroll
                for (int j = 0; j < 8; j++)
                    acc[i][j] = fmaf(wv[i], xv[j], acc[i][j]);
        }
    }
    __syncthreads();

    // dump scores tile into smem ss[64][TP+2]
    float* ss = sbuf;
#pragma unroll
    for (int i = 0; i < 4; i++)
#pragma unroll
        for (int j = 0; j < 8; j++)
            ss[(tk * 4 + i) * (TP + 2) + tp * 8 + j] = acc[i][j];
    __syncthreads();

    // softmax over k, one column per thread (threads 0..127)
    if (tid < TP) {
        const int p = pbase + tid;
        if (p < Pp) {
            float mx = -3.4e38f;
            for (int k = 0; k < Kk; k++) {
                float v = ss[k * (TP + 2) + tid] + sbias[k];
                ss[k * (TP + 2) + tid] = v;
                mx = fmaxf(mx, v);
            }
            float sum = 0.f;
            for (int k = 0; k < Kk; k++) {
                float e = __expf(ss[k * (TP + 2) + tid] - mx);
                ss[k * (TP + 2) + tid] = e;
                sum += e;
            }
            float inv = 1.f / sum;
            for (int k = 0; k < Kk; k++) {
                float sv = ss[k * (TP + 2) + tid] * inv;
                ss[k * (TP + 2) + tid] = sv;
                g_soft[((size_t)n * Kk + k) * Pp + p] = sv;
            }
        } else {
            for (int k = 0; k < Kk; k++) ss[k * (TP + 2) + tid] = 0.f;
        }
    }
    __syncthreads();

    // mass[n,k] partial: row sums of soft tile
    if (tid < Kk) {
        float s = 0.f;
        for (int j = 0; j < TP; j++) s += ss[tid * (TP + 2) + j];
        atomicAdd(&g_mass[n * Kk + tid], s);
    }
}

// ---------------------------------------------------------------------------
// Kernel 2: agg[n,k,c] = sum_p soft[n,k,p] * x[n,c,p]   (A @ B^T per n)
// Block: 256 threads = 16(tk) x 16(tc); micro-tile 4k x 4c; tile 64k x 64c.
// ---------------------------------------------------------------------------
__global__ __launch_bounds__(256) void k_agg(const float* __restrict__ x) {
    __shared__ float as[Kk * (PC + 1)];   // soft chunk [64k][32p] padded
    __shared__ float bs[64 * (PC + 1)];   // x    chunk [64c][32p] padded

    const int n   = blockIdx.y;
    const int c0  = blockIdx.x * 64;
    const int tid = threadIdx.x;
    const int tk  = tid >> 4;
    const int tc  = tid & 15;

    float acc[4][4];
#pragma unroll
    for (int i = 0; i < 4; i++)
#pragma unroll
        for (int j = 0; j < 4; j++) acc[i][j] = 0.f;

    const float* softb = g_soft + (size_t)n * Kk * Pp;
    const float* xb    = x + (size_t)n * Cc * Pp + (size_t)c0 * Pp;

    for (int p0 = 0; p0 < Pp; p0 += PC) {   // 50 chunks, exact
        __syncthreads();
        for (int i = tid; i < Kk * PC; i += 256) {
            int k = i >> 5, pi = i & 31;
            as[k * (PC + 1) + pi] = softb[(size_t)k * Pp + p0 + pi];
        }
        for (int i = tid; i < 64 * PC; i += 256) {
            int ci = i >> 5, pi = i & 31;
            bs[ci * (PC + 1) + pi] = xb[(size_t)ci * Pp + p0 + pi];
        }
        __syncthreads();

#pragma unroll 8
        for (int pi = 0; pi < PC; pi++) {
            float a[4], b[4];
#pragma unroll
            for (int i = 0; i < 4; i++) a[i] = as[(tk * 4 + i) * (PC + 1) + pi];
#pragma unroll
            for (int j = 0; j < 4; j++) b[j] = bs[(tc * 4 + j) * (PC + 1) + pi];
#pragma unroll
            for (int i = 0; i < 4; i++)
#pragma unroll
                for (int j = 0; j < 4; j++)
                    acc[i][j] = fmaf(a[i], b[j], acc[i][j]);
        }
    }

#pragma unroll
    for (int i = 0; i < 4; i++) {
        float4 v = make_float4(acc[i][0], acc[i][1], acc[i][2], acc[i][3]);
        *(float4*)&g_agg[((size_t)n * Kk + tk * 4 + i) * Cc + c0 + tc * 4] = v;
    }
}

// ---------------------------------------------------------------------------
// Kernel 3: vlad = agg - mass*centroid; intra-L2-norm per (n,k) row;
//           accumulate per-n global sumsq.
// One block of 128 threads per (n,k) row; 4 channels per thread.
// ---------------------------------------------------------------------------
__global__ __launch_bounds__(128) void k_vlad(const float* __restrict__ centroids,
                                              float* __restrict__ out) {
    const int n   = blockIdx.x >> 6;
    const int k   = blockIdx.x & 63;
    const int tid = threadIdx.x;

    const float m = g_mass[n * Kk + k];
    const int c = tid * 4;

    float4 a  = *(const float4*)&g_agg[((size_t)n * Kk + k) * Cc + c];
    float4 ce = *(const float4*)&centroids[k * Cc + c];
    float4 v;
    v.x = a.x - m * ce.x;
    v.y = a.y - m * ce.y;
    v.z = a.z - m * ce.z;
    v.w = a.w - m * ce.w;

    float ssq = v.x * v.x + v.y * v.y + v.z * v.z + v.w * v.w;
#pragma unroll
    for (int off = 16; off > 0; off >>= 1)
        ssq += __shfl_xor_sync(0xffffffffu, ssq, off);

    __shared__ float red[4];
    const int warp = tid >> 5, lane = tid & 31;
    if (lane == 0) red[warp] = ssq;
    __syncthreads();
    const float tot = red[0] + red[1] + red[2] + red[3];

    const float t   = fmaxf(sqrtf(tot), EPSF);
    const float inv = 1.f / t;

    float4 o;
    o.x = v.x * inv; o.y = v.y * inv; o.z = v.z * inv; o.w = v.w * inv;
    *(float4*)&out[(size_t)n * (Kk * Cc) + k * Cc + c] = o;

    if (tid == 0) atomicAdd(&g_gsum[n], tot * inv * inv);
}

// ---------------------------------------------------------------------------
// Kernel 4: global L2 rescale per n
// ---------------------------------------------------------------------------
__global__ __launch_bounds__(256) void k_gnorm(float* __restrict__ out) {
    const int n = blockIdx.y;
    const float scale = 1.f / fmaxf(sqrtf(g_gsum[n]), EPSF);
    const int idx = blockIdx.x * blockDim.x + threadIdx.x;   // float4 index
    float4* o = (float4*)(out + (size_t)n * Kk * Cc);
    float4 v = o[idx];
    v.x *= scale; v.y *= scale; v.z *= scale; v.w *= scale;
    o[idx] = v;
}

// ---------------------------------------------------------------------------
extern "C" void kernel_launch(void* const* d_in, const int* in_sizes, int n_in,
                              void* d_out, int out_size) {
    const float* x         = (const float*)d_in[0];  // [32,512,40,40]
    const float* centroids = (const float*)d_in[1];  // [64,512]
    const float* conv_w    = (const float*)d_in[2];  // [64,512]
    const float* conv_b    = (const float*)d_in[3];  // [64]
    float* out = (float*)d_out;                      // [32, 64*512]

    k_zero<<<(Nn * Kk + 255) / 256, 256>>>();

    dim3 g1(NPT, Nn);
    k_scores<<<g1, 256>>>(x, conv_w, conv_b);

    dim3 g2(Cc / 64, Nn);
    k_agg<<<g2, 256>>>(x);

    k_vlad<<<Nn * Kk, 128>>>(centroids, out);

    dim3 g4(Kk * Cc / 4 / 256, Nn);   // 32 x 32
    k_gnorm<<<g4, 256>>>(out);
}